// round 2
// baseline (speedup 1.0000x reference)
#include <cuda_runtime.h>
#include <cuda_bf16.h>

// BERTEmbedding: out[b,l,:] = token_table[seq[b,l],:]
//                           + mean_{g<cnt}(genre_table[gids[seq[b,l],g],:])
//                           + pos_table[l,:]
//
// B=256, L=200, EMBED=128 (32 float4), MAX_G=8.
// One warp handles TWO tokens sharing the same l: (b, l) and (b+128, l).
// Lane k owns float4 at dim 4k. Pos row loaded once, reused for both tokens.
// gids loaded as 2x int4 uniform loads per token instead of 8 scalar loads.

#define SEQ_L 200
#define HALF_B 128
#define NUM_WARPS (HALF_B * SEQ_L)   // 25600
#define MAX_G 8

__global__ __launch_bounds__(256) void bert_embed_kernel(
    const int* __restrict__ seq,          // [256,200]
    const float4* __restrict__ tok_tab,   // [VOCAB,32]
    const float4* __restrict__ gen_tab,   // [21,32]
    const float4* __restrict__ pos_tab,   // [200,32]
    const int4* __restrict__ tgid,        // [VOCAB,8] viewed as [VOCAB,2] int4
    const int* __restrict__ gcnt,         // [VOCAB]
    float4* __restrict__ out)             // [256*200,32]
{
    const int wg = (blockIdx.x * blockDim.x + threadIdx.x) >> 5;
    const int lane = threadIdx.x & 31;
    if (wg >= NUM_WARPS) return;

    const int b = wg / SEQ_L;            // 0..127
    const int l = wg % SEQ_L;
    const int i0 = b * SEQ_L + l;
    const int i1 = i0 + HALF_B * SEQ_L;

    // Level-1 loads (independent)
    const int t0 = __ldg(&seq[i0]);
    const int t1 = __ldg(&seq[i1]);

    // Level-2 loads: all independent of each other — maximize MLP
    const int   c0  = __ldg(&gcnt[t0]);
    const int   c1  = __ldg(&gcnt[t1]);
    const int4  ga0 = __ldg(&tgid[t0 * 2]);
    const int4  gb0 = __ldg(&tgid[t0 * 2 + 1]);
    const int4  ga1 = __ldg(&tgid[t1 * 2]);
    const int4  gb1 = __ldg(&tgid[t1 * 2 + 1]);
    float4 acc0 = __ldg(&tok_tab[t0 * 32 + lane]);
    float4 acc1 = __ldg(&tok_tab[t1 * 32 + lane]);
    const float4 pos = __ldg(&pos_tab[l * 32 + lane]);

    // Genre accumulation for token 0
    int g0[MAX_G] = {ga0.x, ga0.y, ga0.z, ga0.w, gb0.x, gb0.y, gb0.z, gb0.w};
    int g1[MAX_G] = {ga1.x, ga1.y, ga1.z, ga1.w, gb1.x, gb1.y, gb1.z, gb1.w};

    float4 s0 = make_float4(0.f, 0.f, 0.f, 0.f);
    float4 s1 = make_float4(0.f, 0.f, 0.f, 0.f);
    #pragma unroll
    for (int g = 0; g < MAX_G; g++) {
        if (g < c0) {
            const float4 ge = __ldg(&gen_tab[g0[g] * 32 + lane]);  // 10.5KB table, L1-hot
            s0.x += ge.x; s0.y += ge.y; s0.z += ge.z; s0.w += ge.w;
        }
        if (g < c1) {
            const float4 ge = __ldg(&gen_tab[g1[g] * 32 + lane]);
            s1.x += ge.x; s1.y += ge.y; s1.z += ge.z; s1.w += ge.w;
        }
    }

    const float inv0 = 1.0f / (float)c0;
    const float inv1 = 1.0f / (float)c1;

    acc0.x += pos.x + s0.x * inv0;
    acc0.y += pos.y + s0.y * inv0;
    acc0.z += pos.z + s0.z * inv0;
    acc0.w += pos.w + s0.w * inv0;

    acc1.x += pos.x + s1.x * inv1;
    acc1.y += pos.y + s1.y * inv1;
    acc1.z += pos.z + s1.z * inv1;
    acc1.w += pos.w + s1.w * inv1;

    out[i0 * 32 + lane] = acc0;
    out[i1 * 32 + lane] = acc1;
}

extern "C" void kernel_launch(void* const* d_in, const int* in_sizes, int n_in,
                              void* d_out, int out_size) {
    const int*    seq     = (const int*)d_in[0];
    const float4* tok_tab = (const float4*)d_in[1];
    const float4* gen_tab = (const float4*)d_in[2];
    const float4* pos_tab = (const float4*)d_in[3];
    const int4*   tgid    = (const int4*)d_in[4];
    const int*    gcnt    = (const int*)d_in[5];
    float4*       out     = (float4*)d_out;

    const int blocks = (NUM_WARPS * 32 + 255) / 256;  // 3200
    bert_embed_kernel<<<blocks, 256>>>(seq, tok_tab, gen_tab, pos_tab, tgid, gcnt, out);
}